// round 7
// baseline (speedup 1.0000x reference)
#include <cuda_runtime.h>
#include <math.h>

// Problem shapes (fixed by dataset)
#define SS 2048
#define BB 32
#define HH 1024

// u GEMM tiling: 64 o-chunks of 16
#define NOB 64
#define OC  16

#define GRID 148   // persistent co-resident blocks for scores+softmax

// Scratch (static __device__ — no allocations allowed)
__device__ float g_u_part[NOB][BB * HH];  // 8 MB (L2-resident)
__device__ float g_u[BB * HH];            // 128 KB
__device__ float g_scores[BB * SS];       // 256 KB
__device__ unsigned g_sync[2];            // [0]=task counter, [1]=barrier

// ---------------------------------------------------------------------------
// K_A: u_part[j][b][h] = sum_{o in chunk j} hidden[b,o] * W[o,h]
// grid NOB=64 blocks, 1024 threads (t == h). W read exactly once.
// ---------------------------------------------------------------------------
__global__ void __launch_bounds__(1024) k_upart(const float* __restrict__ hidden,
                                                const float* __restrict__ W) {
    __shared__ float hs[OC * BB];
    const int o0 = blockIdx.x * OC;
    const int t = threadIdx.x;

    if (t < OC * BB) {
        int o = t >> 5, b = t & 31;
        hs[t] = hidden[b * HH + o0 + o];
    }
    __syncthreads();

    float acc[BB];
#pragma unroll
    for (int b = 0; b < BB; ++b) acc[b] = 0.f;

#pragma unroll
    for (int o = 0; o < OC; ++o) {
        float w = W[(size_t)(o0 + o) * HH + t];
#pragma unroll
        for (int b = 0; b < BB; ++b) acc[b] = fmaf(hs[o * BB + b], w, acc[b]);
    }

#pragma unroll
    for (int b = 0; b < BB; ++b) g_u_part[blockIdx.x][b * HH + t] = acc[b];
}

// ---------------------------------------------------------------------------
// K_B: u[i] = sum over the NOB partials (8 MB, L2-hot). grid 128, block 256.
// ---------------------------------------------------------------------------
__global__ void __launch_bounds__(256) k_ureduce() {
    int i = blockIdx.x * 256 + threadIdx.x;  // i < BB*HH
    float s = 0.f;
#pragma unroll
    for (int p = 0; p < NOB; ++p) s += g_u_part[p][i];
    g_u[i] = s;
}

// ---------------------------------------------------------------------------
// K_C: persistent scores + fused softmax.
// Phase 1 (HBM-bound): dynamic single-s tasks via atomic counter. warp w <->
// batch b = w; u[b] pinned in 8 float4 regs for the whole kernel. Each task
// streams one contiguous 128 KB slab enc[s,:,:] (one 4 KB row per warp,
// 8x LDG.128, __ldcs evict-first).
// Barrier: single grid-wide arrive/spin among 148 equal-work blocks.
// Phase 2: blocks 0..31 do the 2048-wide softmax for b = blk, write d_out.
// ---------------------------------------------------------------------------
__global__ void __launch_bounds__(1024, 1)
k_scores_softmax(const float* __restrict__ enc, float* __restrict__ out) {
    const int t = threadIdx.x;
    const int warp = t >> 5;
    const int lane = t & 31;
    const int b = warp;

    __shared__ int s_task;
    __shared__ float red[32];

    // u[b] -> registers, once
    const float4* ub = reinterpret_cast<const float4*>(g_u + b * HH);
    float4 u[8];
#pragma unroll
    for (int c = 0; c < 8; ++c) u[c] = ub[c * 32 + lane];

    // ---- Phase 1: dynamic task loop over s ----
    for (;;) {
        if (t == 0) s_task = (int)atomicAdd(&g_sync[0], 1u);
        __syncthreads();
        const int s = s_task;
        __syncthreads();  // protect s_task before next overwrite
        if (s >= SS) break;

        const float4* r =
            reinterpret_cast<const float4*>(enc + ((size_t)s * BB + b) * HH);
        float a = 0.f;
#pragma unroll
        for (int c = 0; c < 8; ++c) {
            float4 e = __ldcs(&r[c * 32 + lane]);
            a += e.x * u[c].x + e.y * u[c].y + e.z * u[c].z + e.w * u[c].w;
        }
#pragma unroll
        for (int off = 16; off; off >>= 1)
            a += __shfl_xor_sync(0xFFFFFFFFu, a, off);
        if (lane == 0) g_scores[b * SS + s] = a;
    }

    // ---- Grid barrier (148 equal-work blocks, arrivals are tight) ----
    __syncthreads();
    if (t == 0) {
        __threadfence();                         // release scores
        atomicAdd(&g_sync[1], 1u);
        while (atomicAdd(&g_sync[1], 0u) < GRID) __nanosleep(32);
        __threadfence();                         // acquire
    }
    __syncthreads();

    // ---- Phase 2: softmax, blocks 0..31 (b = blockIdx.x) ----
    if (blockIdx.x < BB) {
        const int bb = blockIdx.x;
        float v0 = g_scores[bb * SS + t];
        float v1 = g_scores[bb * SS + t + 1024];

        float m = fmaxf(v0, v1);
#pragma unroll
        for (int off = 16; off; off >>= 1)
            m = fmaxf(m, __shfl_xor_sync(0xFFFFFFFFu, m, off));
        if (lane == 0) red[warp] = m;
        __syncthreads();
        if (warp == 0) {
            float x = red[lane];
#pragma unroll
            for (int off = 16; off; off >>= 1)
                x = fmaxf(x, __shfl_xor_sync(0xFFFFFFFFu, x, off));
            if (lane == 0) red[0] = x;
        }
        __syncthreads();
        const float bm = red[0];
        __syncthreads();

        v0 = __expf(v0 - bm);
        v1 = __expf(v1 - bm);
        float s = v0 + v1;
#pragma unroll
        for (int off = 16; off; off >>= 1)
            s += __shfl_xor_sync(0xFFFFFFFFu, s, off);
        if (lane == 0) red[warp] = s;
        __syncthreads();
        if (warp == 0) {
            float x = red[lane];
#pragma unroll
            for (int off = 16; off; off >>= 1)
                x += __shfl_xor_sync(0xFFFFFFFFu, x, off);
            if (lane == 0) red[0] = x;
        }
        __syncthreads();
        const float inv = 1.f / red[0];

        out[bb * SS + t]        = v0 * inv;
        out[bb * SS + t + 1024] = v1 * inv;
    }
}

// ---------------------------------------------------------------------------
// Inputs (metadata order): hidden [B,H], encoder_outputs [S,B,H], W [H,H], b [H]
// The bias input is mathematically irrelevant (softmax shift invariance).
// ---------------------------------------------------------------------------
extern "C" void kernel_launch(void* const* d_in, const int* in_sizes, int n_in,
                              void* d_out, int out_size) {
    const float* hidden = (const float*)d_in[0];
    const float* enc    = (const float*)d_in[1];
    const float* W      = (const float*)d_in[2];
    float* out          = (float*)d_out;

    // Zero task counter + barrier each invocation (captured graph node).
    void* sync_ptr;
    cudaGetSymbolAddress(&sync_ptr, g_sync);
    cudaMemsetAsync(sync_ptr, 0, sizeof(unsigned) * 2);

    k_upart<<<NOB, 1024>>>(hidden, W);
    k_ureduce<<<(BB * HH) / 256, 256>>>();
    k_scores_softmax<<<GRID, 1024>>>(enc, out);
}

// round 8
// speedup vs baseline: 1.1486x; 1.1486x over previous
#include <cuda_runtime.h>
#include <math.h>

// Problem shapes (fixed by dataset)
#define SS 2048
#define BB 32
#define HH 1024

// u GEMM tiling: 32 o-chunks of 32, 4 h-chunks of 256
#define NOB 32
#define OC  32

// Persistent scores kernel: 148 co-scheduled blocks, 1024 s-pair tasks
#define GRID 148
#define FAT  136   // 136*7 + 12*6 = 1024

// Scratch (static __device__ — no allocations allowed)
__device__ float g_u_part[NOB][BB * HH];  // 4 MB (L2-resident)
__device__ float g_u[BB * HH];            // 128 KB
__device__ float g_scores[BB * SS];       // 256 KB

// ---------------------------------------------------------------------------
// K_A: u_part[j][b][h] = sum_{o in chunk j} hidden[b,o] * W[o,h]
// grid (HH/256, NOB) = (4, 32) = 128 blocks, 256 threads, NO launch_bounds
// cap so acc[32] stays in registers (the 1024-thread version spilled to
// local memory -> 13.8us). W read exactly once, fully coalesced.
// ---------------------------------------------------------------------------
__global__ void k_upart(const float* __restrict__ hidden,
                        const float* __restrict__ W) {
    __shared__ float hs[OC * BB];  // hs[o*BB + b] = hidden[b, o0+o]
    const int t = threadIdx.x;
    const int h = blockIdx.x * 256 + t;
    const int o0 = blockIdx.y * OC;

    // 256 threads load OC*BB = 1024 hidden values
    for (int i = t; i < OC * BB; i += 256) {
        int o = i >> 5, b = i & 31;
        hs[i] = hidden[b * HH + o0 + o];
    }
    __syncthreads();

    float acc[BB];
#pragma unroll
    for (int b = 0; b < BB; ++b) acc[b] = 0.f;

#pragma unroll 4
    for (int o = 0; o < OC; ++o) {
        float w = W[(size_t)(o0 + o) * HH + h];
#pragma unroll
        for (int b = 0; b < BB; ++b) acc[b] = fmaf(hs[o * BB + b], w, acc[b]);
    }

#pragma unroll
    for (int b = 0; b < BB; ++b) g_u_part[blockIdx.y][b * HH + h] = acc[b];
}

// ---------------------------------------------------------------------------
// K_B: u[i] = sum over the NOB partials (4 MB, L2-hot). grid 128, block 256.
// ---------------------------------------------------------------------------
__global__ void __launch_bounds__(256) k_ureduce() {
    int i = blockIdx.x * 256 + threadIdx.x;  // i < BB*HH = 32768
    float s = 0.f;
#pragma unroll
    for (int p = 0; p < NOB; ++p) s += g_u_part[p][i];
    g_u[i] = s;
}

// ---------------------------------------------------------------------------
// K_C (dominant, HBM-bound): scores[b,s] = u[b] . enc[s,b,:]
// PERSISTENT: grid 148 x 1024 threads, warp w <-> batch b = w. u[b] in 8
// float4 regs once per block. Static 7/6 consecutive s-pair tasks, NO
// intra-phase syncs (dynamic per-task sync version measured +5us: pipeline
// drain between tasks). enc via __ldcs (stream, evict-first).
// ---------------------------------------------------------------------------
__global__ void __launch_bounds__(1024, 1)
k_scores(const float* __restrict__ enc, float* __restrict__ scores) {
    const int warp = threadIdx.x >> 5;
    const int lane = threadIdx.x & 31;
    const int b = warp;
    const int blk = blockIdx.x;

    const float4* ub = reinterpret_cast<const float4*>(g_u + b * HH);
    float4 u[8];
#pragma unroll
    for (int c = 0; c < 8; ++c) u[c] = ub[c * 32 + lane];

    int start, cnt;
    if (blk < FAT) { start = blk * 7; cnt = 7; }
    else           { start = FAT * 7 + (blk - FAT) * 6; cnt = 6; }

    for (int k = 0; k < cnt; ++k) {
        const int s0 = (start + k) * 2;
        const float4* r0 =
            reinterpret_cast<const float4*>(enc + ((size_t)s0 * BB + b) * HH);
        const float4* r1 =
            reinterpret_cast<const float4*>(enc + ((size_t)(s0 + 1) * BB + b) * HH);

        float a0 = 0.f, a1 = 0.f;
#pragma unroll
        for (int c = 0; c < 8; ++c) {
            float4 e0 = __ldcs(&r0[c * 32 + lane]);
            float4 e1 = __ldcs(&r1[c * 32 + lane]);
            a0 += e0.x * u[c].x + e0.y * u[c].y + e0.z * u[c].z + e0.w * u[c].w;
            a1 += e1.x * u[c].x + e1.y * u[c].y + e1.z * u[c].z + e1.w * u[c].w;
        }
#pragma unroll
        for (int off = 16; off; off >>= 1) {
            a0 += __shfl_xor_sync(0xFFFFFFFFu, a0, off);
            a1 += __shfl_xor_sync(0xFFFFFFFFu, a1, off);
        }
        if (lane == 0) {
            scores[b * SS + s0]     = a0;
            scores[b * SS + s0 + 1] = a1;
        }
    }
}

// ---------------------------------------------------------------------------
// K_D: per-b softmax over s (row length 2048). grid BB, block 1024.
// Writes d_out directly ([B,1,S] is contiguous [B*S]).
// ---------------------------------------------------------------------------
__global__ void __launch_bounds__(1024) k_softmax(float* __restrict__ out) {
    const int b = blockIdx.x;
    const int t = threadIdx.x;
    const int warp = t >> 5;
    const int lane = t & 31;
    __shared__ float red[32];

    float v0 = g_scores[b * SS + t];
    float v1 = g_scores[b * SS + t + 1024];

    // max
    float m = fmaxf(v0, v1);
#pragma unroll
    for (int off = 16; off; off >>= 1)
        m = fmaxf(m, __shfl_xor_sync(0xFFFFFFFFu, m, off));
    if (lane == 0) red[warp] = m;
    __syncthreads();
    if (warp == 0) {
        float x = red[lane];
#pragma unroll
        for (int off = 16; off; off >>= 1)
            x = fmaxf(x, __shfl_xor_sync(0xFFFFFFFFu, x, off));
        if (lane == 0) red[0] = x;
    }
    __syncthreads();
    const float bm = red[0];
    __syncthreads();  // before reusing red[]

    // exp + sum
    v0 = __expf(v0 - bm);
    v1 = __expf(v1 - bm);
    float s = v0 + v1;
#pragma unroll
    for (int off = 16; off; off >>= 1)
        s += __shfl_xor_sync(0xFFFFFFFFu, s, off);
    if (lane == 0) red[warp] = s;
    __syncthreads();
    if (warp == 0) {
        float x = red[lane];
#pragma unroll
        for (int off = 16; off; off >>= 1)
            x += __shfl_xor_sync(0xFFFFFFFFu, x, off);
        if (lane == 0) red[0] = x;
    }
    __syncthreads();
    const float inv = 1.f / red[0];

    out[b * SS + t]        = v0 * inv;
    out[b * SS + t + 1024] = v1 * inv;
}

// ---------------------------------------------------------------------------
// Inputs (metadata order): hidden [B,H], encoder_outputs [S,B,H], W [H,H], b [H]
// The bias input is mathematically irrelevant (softmax shift invariance).
// ---------------------------------------------------------------------------
extern "C" void kernel_launch(void* const* d_in, const int* in_sizes, int n_in,
                              void* d_out, int out_size) {
    const float* hidden = (const float*)d_in[0];
    const float* enc    = (const float*)d_in[1];
    const float* W      = (const float*)d_in[2];
    float* out          = (float*)d_out;

    k_upart<<<dim3(HH / 256, NOB), 256>>>(hidden, W);
    k_ureduce<<<(BB * HH) / 256, 256>>>();

    float* scores_ptr;
    cudaGetSymbolAddress((void**)&scores_ptr, g_scores);
    k_scores<<<GRID, 1024>>>(enc, scores_ptr);
    k_softmax<<<BB, 1024>>>(out);
}

// round 9
// speedup vs baseline: 1.1520x; 1.0029x over previous
#include <cuda_runtime.h>
#include <math.h>

// Problem shapes (fixed by dataset)
#define SS 2048
#define BB 32
#define HH 1024

// u GEMM tiling: 32 o-chunks of 32, 4 h-chunks of 256
#define NOB 32
#define OC  32

#define GRID 148   // persistent co-resident blocks for scores+softmax

// Scratch (static __device__ — no allocations allowed)
__device__ float g_u_part[NOB][BB * HH];  // 4 MB (L2-resident)
__device__ float g_u[BB * HH];            // 128 KB
__device__ float g_scores[BB * SS];       // 256 KB
__device__ unsigned g_bar;                // single grid-barrier counter

// ---------------------------------------------------------------------------
// K_A: u_part[j][b][h] = sum_{o in chunk j} hidden[b,o] * W[o,h]
// grid (HH/256, NOB) = (4, 32) = 128 blocks, 256 threads, NO launch_bounds
// cap so acc[32] stays in registers (reg-capped version spilled -> 13.8us).
// W read exactly once, fully coalesced.
// ---------------------------------------------------------------------------
__global__ void k_upart(const float* __restrict__ hidden,
                        const float* __restrict__ W) {
    __shared__ float hs[OC * BB];  // hs[o*BB + b] = hidden[b, o0+o]
    const int t = threadIdx.x;
    const int h = blockIdx.x * 256 + t;
    const int o0 = blockIdx.y * OC;

    for (int i = t; i < OC * BB; i += 256) {
        int o = i >> 5, b = i & 31;
        hs[i] = hidden[b * HH + o0 + o];
    }
    __syncthreads();

    float acc[BB];
#pragma unroll
    for (int b = 0; b < BB; ++b) acc[b] = 0.f;

#pragma unroll 4
    for (int o = 0; o < OC; ++o) {
        float w = W[(size_t)(o0 + o) * HH + h];
#pragma unroll
        for (int b = 0; b < BB; ++b) acc[b] = fmaf(hs[o * BB + b], w, acc[b]);
    }

#pragma unroll
    for (int b = 0; b < BB; ++b) g_u_part[blockIdx.y][b * HH + h] = acc[b];
}

// ---------------------------------------------------------------------------
// K_B: u[i] = sum over the NOB partials (4 MB, L2-hot). grid 128, block 256.
// ---------------------------------------------------------------------------
__global__ void __launch_bounds__(256) k_ureduce() {
    int i = blockIdx.x * 256 + threadIdx.x;  // i < BB*HH = 32768
    float s = 0.f;
#pragma unroll
    for (int p = 0; p < NOB; ++p) s += g_u_part[p][i];
    g_u[i] = s;
}

// ---------------------------------------------------------------------------
// K_C: persistent scores (static, sync-free) + ONE grid barrier + softmax.
// Scores: warp w <-> batch b = w; u[b] pinned in 8 float4 regs. Tasks are
// single s, interleaved s = blk + k*GRID (14 or 13 per block -> tail
// imbalance halved vs pair tasks). Each task = one contiguous 128 KB slab
// enc[s,:,:], one 4 KB row per warp (8x LDG.128, __ldcs evict-first).
// Softmax: after the barrier, blocks 0..31 normalize row b = blockIdx.x.
// ---------------------------------------------------------------------------
__global__ void __launch_bounds__(1024, 1)
k_scores_softmax(const float* __restrict__ enc, float* __restrict__ out) {
    const int t = threadIdx.x;
    const int warp = t >> 5;
    const int lane = t & 31;
    const int b = warp;
    const int blk = blockIdx.x;

    __shared__ float red[32];

    // u[b] -> registers, once per block
    const float4* ub = reinterpret_cast<const float4*>(g_u + b * HH);
    float4 u[8];
#pragma unroll
    for (int c = 0; c < 8; ++c) u[c] = ub[c * 32 + lane];

    // ---- Phase 1: scores, static interleaved tasks, no syncs ----
    for (int s = blk; s < SS; s += GRID) {
        const float4* r =
            reinterpret_cast<const float4*>(enc + ((size_t)s * BB + b) * HH);
        float a = 0.f;
#pragma unroll
        for (int c = 0; c < 8; ++c) {
            float4 e = __ldcs(&r[c * 32 + lane]);
            a += e.x * u[c].x + e.y * u[c].y + e.z * u[c].z + e.w * u[c].w;
        }
#pragma unroll
        for (int off = 16; off; off >>= 1)
            a += __shfl_xor_sync(0xFFFFFFFFu, a, off);
        if (lane == 0) g_scores[b * SS + s] = a;
    }

    // ---- ONE grid barrier among 148 equal-work blocks ----
    __syncthreads();
    if (t == 0) {
        __threadfence();                       // release scores
        atomicAdd(&g_bar, 1u);
        while (atomicAdd(&g_bar, 0u) < GRID) __nanosleep(32);
        __threadfence();                       // acquire
    }
    __syncthreads();

    // ---- Phase 2: softmax (blocks 0..31, batch bb = blk) ----
    if (blk < BB) {
        const int bb = blk;
        float v0 = g_scores[bb * SS + t];
        float v1 = g_scores[bb * SS + t + 1024];

        float m = fmaxf(v0, v1);
#pragma unroll
        for (int off = 16; off; off >>= 1)
            m = fmaxf(m, __shfl_xor_sync(0xFFFFFFFFu, m, off));
        if (lane == 0) red[warp] = m;
        __syncthreads();
        if (warp == 0) {
            float x = red[lane];
#pragma unroll
            for (int off = 16; off; off >>= 1)
                x = fmaxf(x, __shfl_xor_sync(0xFFFFFFFFu, x, off));
            if (lane == 0) red[0] = x;
        }
        __syncthreads();
        const float bm = red[0];
        __syncthreads();  // before reusing red[]

        v0 = __expf(v0 - bm);
        v1 = __expf(v1 - bm);
        float s = v0 + v1;
#pragma unroll
        for (int off = 16; off; off >>= 1)
            s += __shfl_xor_sync(0xFFFFFFFFu, s, off);
        if (lane == 0) red[warp] = s;
        __syncthreads();
        if (warp == 0) {
            float x = red[lane];
#pragma unroll
            for (int off = 16; off; off >>= 1)
                x += __shfl_xor_sync(0xFFFFFFFFu, x, off);
            if (lane == 0) red[0] = x;
        }
        __syncthreads();
        const float inv = 1.f / red[0];

        out[bb * SS + t]        = v0 * inv;
        out[bb * SS + t + 1024] = v1 * inv;
    }
}

// ---------------------------------------------------------------------------
// Inputs (metadata order): hidden [B,H], encoder_outputs [S,B,H], W [H,H], b [H]
// The bias input is mathematically irrelevant (softmax shift invariance).
// ---------------------------------------------------------------------------
extern "C" void kernel_launch(void* const* d_in, const int* in_sizes, int n_in,
                              void* d_out, int out_size) {
    const float* hidden = (const float*)d_in[0];
    const float* enc    = (const float*)d_in[1];
    const float* W      = (const float*)d_in[2];
    float* out          = (float*)d_out;

    // Zero the barrier counter each invocation (captured as a graph node).
    void* bar_ptr;
    cudaGetSymbolAddress(&bar_ptr, g_bar);
    cudaMemsetAsync(bar_ptr, 0, sizeof(unsigned));

    k_upart<<<dim3(HH / 256, NOB), 256>>>(hidden, W);
    k_ureduce<<<(BB * HH) / 256, 256>>>();
    k_scores_softmax<<<GRID, 1024>>>(enc, out);
}